// round 6
// baseline (speedup 1.0000x reference)
#include <cuda_runtime.h>
#include <math.h>

#define N 8192
#define N4 (N / 4)

// ---- shared tiling: 64x64 for both passes ----
#define T 64
#define NB (N / T)                      // 128
#define NPAIRS (NB * (NB + 1) / 2)      // 8256

__device__ float g_rowsum[N];
__device__ float g_dinv[N];

__device__ __forceinline__ int pair_offset(int bi) {
    return bi * NB - (bi * (bi - 1)) / 2;
}

__device__ __forceinline__ void decode_pair(int p, int& bi, int& bj) {
    float disc = (float)((2 * NB + 1) * (2 * NB + 1) - 8 * p);
    int b = (int)(((float)(2 * NB + 1) - sqrtf(disc)) * 0.5f);
    if (b < 0) b = 0;
    if (b > NB - 1) b = NB - 1;
    while (b + 1 <= NB - 1 && pair_offset(b + 1) <= p) b++;
    while (b > 0 && pair_offset(b) > p) b--;
    bi = b;
    bj = bi + (p - pair_offset(b));
}

// Pass 1: rowsum[i] = sum_j max(adj[i,j], adj[j,i]) + (i==j). 64x64 tile pairs, 256 thr.
__global__ __launch_bounds__(256) void pass1_kernel(const float4* __restrict__ adj4) {
    int bi, bj;
    decode_pair(blockIdx.x, bi, bj);
    const int r0 = bi * T;
    const int c0 = bj * T;

    const int t    = threadIdx.x;
    const int q    = t & 15;
    const int rr   = t >> 4;
    const int lane = t & 31;
    const int wid  = t >> 5;

    __shared__ float Bs[T][T + 1];
    __shared__ float Cs[8][T];

    float4 a[4], b[4];
    #pragma unroll
    for (int k = 0; k < 4; k++) {
        int row = rr + 16 * k;
        a[k] = adj4[(size_t)(r0 + row) * N4 + (c0 >> 2) + q];
        b[k] = adj4[(size_t)(c0 + row) * N4 + (r0 >> 2) + q];
    }
    #pragma unroll
    for (int k = 0; k < 4; k++) {
        int row = rr + 16 * k;
        Bs[row][4 * q + 0] = b[k].x;
        Bs[row][4 * q + 1] = b[k].y;
        Bs[row][4 * q + 2] = b[k].z;
        Bs[row][4 * q + 3] = b[k].w;
    }
    __syncthreads();

    const bool diag = (bi == bj);
    float cx = 0.0f, cy = 0.0f, cz = 0.0f, cw = 0.0f;
    #pragma unroll
    for (int k = 0; k < 4; k++) {
        int row = rr + 16 * k;
        float4 m;
        m.x = fmaxf(a[k].x, Bs[4 * q + 0][row]);
        m.y = fmaxf(a[k].y, Bs[4 * q + 1][row]);
        m.z = fmaxf(a[k].z, Bs[4 * q + 2][row]);
        m.w = fmaxf(a[k].w, Bs[4 * q + 3][row]);
        if (diag) {
            if (4 * q + 0 == row) m.x += 1.0f;
            if (4 * q + 1 == row) m.y += 1.0f;
            if (4 * q + 2 == row) m.z += 1.0f;
            if (4 * q + 3 == row) m.w += 1.0f;
        }

        float rs = (m.x + m.y) + (m.z + m.w);
        rs += __shfl_down_sync(0xffffffffu, rs, 8, 16);
        rs += __shfl_down_sync(0xffffffffu, rs, 4, 16);
        rs += __shfl_down_sync(0xffffffffu, rs, 2, 16);
        rs += __shfl_down_sync(0xffffffffu, rs, 1, 16);
        if (q == 0) atomicAdd(&g_rowsum[r0 + row], rs);

        cx += m.x; cy += m.y; cz += m.z; cw += m.w;
    }

    if (!diag) {
        cx += __shfl_xor_sync(0xffffffffu, cx, 16);
        cy += __shfl_xor_sync(0xffffffffu, cy, 16);
        cz += __shfl_xor_sync(0xffffffffu, cz, 16);
        cw += __shfl_xor_sync(0xffffffffu, cw, 16);
        if (lane < 16) {
            Cs[wid][4 * q + 0] = cx;
            Cs[wid][4 * q + 1] = cy;
            Cs[wid][4 * q + 2] = cz;
            Cs[wid][4 * q + 3] = cw;
        }
        __syncthreads();
        if (t < T) {
            float s = 0.0f;
            #pragma unroll
            for (int w = 0; w < 8; w++) s += Cs[w][t];
            atomicAdd(&g_rowsum[c0 + t], s);
        }
    }
}

__global__ void dinv_kernel() {
    int i = blockIdx.x * blockDim.x + threadIdx.x;
    if (i < N) {
        float rs = g_rowsum[i];
        g_dinv[i] = (rs > 0.0f) ? rsqrtf(rs) : 0.0f;
    }
}

// Pass 2: out[i,j] = d[i]*d[j]*(max(adj[i,j],adj[j,i]) + (i==j)).
// 64x64 tile pairs, 512 threads, MLP_p1=4, smem reused for the transpose stage.
__global__ __launch_bounds__(512) void pass2_kernel(const float4* __restrict__ adj4,
                                                    float4* __restrict__ out4) {
    int bi, bj;
    decode_pair(blockIdx.x, bi, bj);
    const int r0 = bi * T;
    const int c0 = bj * T;

    const int t  = threadIdx.x;
    const int q  = t & 15;       // float4 column 0..15
    const int rr = t >> 4;       // row group 0..31

    __shared__ float Bs[T][T + 1];   // b staging, then reused for v transpose

    float4 a[2], b[2];
    #pragma unroll
    for (int k = 0; k < 2; k++) {
        int row = rr + 32 * k;
        a[k] = adj4[(size_t)(r0 + row) * N4 + (c0 >> 2) + q];
        b[k] = adj4[(size_t)(c0 + row) * N4 + (r0 >> 2) + q];
    }
    #pragma unroll
    for (int k = 0; k < 2; k++) {
        int row = rr + 32 * k;
        Bs[row][4 * q + 0] = b[k].x;
        Bs[row][4 * q + 1] = b[k].y;
        Bs[row][4 * q + 2] = b[k].z;
        Bs[row][4 * q + 3] = b[k].w;
    }
    __syncthreads();

    const bool diag = (bi == bj);
    const float4 dj4 = ((const float4*)g_dinv)[(c0 >> 2) + q];

    float4 v[2];
    #pragma unroll
    for (int k = 0; k < 2; k++) {
        int row = rr + 32 * k;
        float4 m;
        m.x = fmaxf(a[k].x, Bs[4 * q + 0][row]);
        m.y = fmaxf(a[k].y, Bs[4 * q + 1][row]);
        m.z = fmaxf(a[k].z, Bs[4 * q + 2][row]);
        m.w = fmaxf(a[k].w, Bs[4 * q + 3][row]);
        if (diag) {
            if (4 * q + 0 == row) m.x += 1.0f;
            if (4 * q + 1 == row) m.y += 1.0f;
            if (4 * q + 2 == row) m.z += 1.0f;
            if (4 * q + 3 == row) m.w += 1.0f;
        }
        const float di = g_dinv[r0 + row];
        v[k].x = di * dj4.x * m.x;
        v[k].y = di * dj4.y * m.y;
        v[k].z = di * dj4.z * m.z;
        v[k].w = di * dj4.w * m.w;
        __stcs(&out4[(size_t)(r0 + row) * N4 + (c0 >> 2) + q], v[k]);
    }

    if (!diag) {
        __syncthreads();   // all reads of Bs (b data) done; safe to overwrite
        #pragma unroll
        for (int k = 0; k < 2; k++) {
            int row = rr + 32 * k;
            Bs[row][4 * q + 0] = v[k].x;
            Bs[row][4 * q + 1] = v[k].y;
            Bs[row][4 * q + 2] = v[k].z;
            Bs[row][4 * q + 3] = v[k].w;
        }
        __syncthreads();
        #pragma unroll
        for (int k = 0; k < 2; k++) {
            int row = rr + 32 * k;
            float4 tr;
            tr.x = Bs[4 * q + 0][row];
            tr.y = Bs[4 * q + 1][row];
            tr.z = Bs[4 * q + 2][row];
            tr.w = Bs[4 * q + 3][row];
            __stcs(&out4[(size_t)(c0 + row) * N4 + (r0 >> 2) + q], tr);
        }
    }
}

extern "C" void kernel_launch(void* const* d_in, const int* in_sizes, int n_in,
                              void* d_out, int out_size) {
    const float4* adj4 = (const float4*)d_in[0];
    float4* out4 = (float4*)d_out;

    void* rowsum_ptr = nullptr;
    cudaGetSymbolAddress(&rowsum_ptr, g_rowsum);
    cudaMemsetAsync(rowsum_ptr, 0, N * sizeof(float));

    pass1_kernel<<<NPAIRS, 256>>>(adj4);
    dinv_kernel<<<N / 256, 256>>>();
    pass2_kernel<<<NPAIRS, 512>>>(adj4, out4);
}